// round 10
// baseline (speedup 1.0000x reference)
#include <cuda_runtime.h>
#include <cuda_bf16.h>
#include <cstdint>

// SimCLR loss via mma.sync bf16, upper-triangle Gram, ticket-balanced
// persistent CTAs. 512 threads/CTA (4 warps/SMSP) for latency hiding.
// B=4096, D=128, N=8192, T=0.5.
//   k1: row-normalize -> g_znh bf16 (2MB, L2-resident); resets ticket
//   k2: 148 persistent CTAs pull tiles (rt<=jt); per tile: HMMA 128x128x128,
//       exp(2*cos-2), row-part -> S[jt][rt], col-part -> S[rt][jt]
//   k3: fused finalize: per-row sums + log - pos; last block sums partials

#define NROWS 8192
#define BHALF 4096
#define NT 2080              // 64*65/2 upper-triangle 128x128 tiles
#define TSTRIDE 272          // smem tile row stride bytes (128 bf16 + 16B pad)
#define TILE_BYTES (128 * TSTRIDE)

__device__ uint4 g_znh[NROWS * 16];
__device__ float g_S[64 * 64 * 128];   // [a][b][i]: contribution to row b*128+i from block a
__device__ float g_pos[NROWS];
__device__ float g_part[64];
__device__ int g_ticket;
__device__ int g_done;

__device__ __forceinline__ uint32_t smem_u32(const void* p) {
    uint32_t a;
    asm("{ .reg .u64 t; cvta.to.shared.u64 t, %1; cvt.u32.u64 %0, t; }" : "=r"(a) : "l"(p));
    return a;
}
__device__ __forceinline__ void cpasync16(uint32_t dst, const void* src) {
    asm volatile("cp.async.cg.shared.global [%0], [%1], 16;"
                 :: "r"(dst), "l"(__cvta_generic_to_global(src)) : "memory");
}
__device__ __forceinline__ void ldm_x4(uint32_t* r, uint32_t addr) {
    asm volatile("ldmatrix.sync.aligned.m8n8.x4.shared.b16 {%0,%1,%2,%3}, [%4];"
                 : "=r"(r[0]), "=r"(r[1]), "=r"(r[2]), "=r"(r[3]) : "r"(addr));
}
__device__ __forceinline__ void mma16816(float* c, const uint32_t* a, const uint32_t* b) {
    asm volatile(
        "mma.sync.aligned.m16n8k16.row.col.f32.bf16.bf16.f32 "
        "{%0,%1,%2,%3}, {%4,%5,%6,%7}, {%8,%9}, {%0,%1,%2,%3};"
        : "+f"(c[0]), "+f"(c[1]), "+f"(c[2]), "+f"(c[3])
        : "r"(a[0]), "r"(a[1]), "r"(a[2]), "r"(a[3]), "r"(b[0]), "r"(b[1]));
}

// tile index t (0..2079) -> (rt, jt), rt<=jt; offset(r) = r*(129-r)/2
__device__ __forceinline__ void tile_rc(int t, int& rt, int& jt) {
    int r = (int)((129.0f - sqrtf((float)(16641 - 8 * t))) * 0.5f);
    while (r > 0 && r * (129 - r) / 2 > t) r--;
    while ((r + 1) * (129 - (r + 1)) / 2 <= t) r++;
    rt = r;
    jt = r + (t - r * (129 - r) / 2);
}

// ---------------- Kernel 1: normalize -> bf16 (4 rows/warp, MLP=4) ----------------
__global__ void k_normalize(const float* __restrict__ zi, const float* __restrict__ zj) {
    if (blockIdx.x == 0 && threadIdx.x == 0) g_ticket = 0;   // reset ticket each launch
    int gw = (blockIdx.x * blockDim.x + threadIdx.x) >> 5;   // 0..2047
    int lane = threadIdx.x & 31;
    int r0 = gw * 4;
    if (r0 >= NROWS) return;
    const float* base = (r0 < BHALF) ? zi : (zj - (size_t)BHALF * 128);
    float4 v[4];
    #pragma unroll
    for (int k = 0; k < 4; k++)
        v[k] = reinterpret_cast<const float4*>(base + (size_t)(r0 + k) * 128)[lane];
    #pragma unroll
    for (int k = 0; k < 4; k++) {
        float ss = v[k].x * v[k].x + v[k].y * v[k].y + v[k].z * v[k].z + v[k].w * v[k].w;
        #pragma unroll
        for (int off = 16; off > 0; off >>= 1)
            ss += __shfl_xor_sync(0xFFFFFFFFu, ss, off);
        float s = 1.0f / fmaxf(sqrtf(ss), 1e-8f);
        __nv_bfloat162 h0 = __floats2bfloat162_rn(v[k].x * s, v[k].y * s);
        __nv_bfloat162 h1 = __floats2bfloat162_rn(v[k].z * s, v[k].w * s);
        uint2 o;
        o.x = *reinterpret_cast<uint32_t*>(&h0);
        o.y = *reinterpret_cast<uint32_t*>(&h1);
        reinterpret_cast<uint2*>(g_znh)[(size_t)(r0 + k) * 32 + lane] = o;
    }
}

__device__ __forceinline__ void load_tile_async(uint32_t sm_tile, int row0, int tid) {
    #pragma unroll
    for (int it = 0; it < 4; it++) {
        int i = tid + it * 512;
        int row = i >> 4;
        int c = i & 15;
        cpasync16(sm_tile + row * TSTRIDE + c * 16, &g_znh[(size_t)(row0 + row) * 16 + c]);
    }
}

// ---------------- Kernel 2: persistent triangular Gram (512 threads) ----------------
__global__ void __launch_bounds__(512, 1) k_gram(void) {
    extern __shared__ char smem[];
    const uint32_t smBase = smem_u32(smem);   // A0 | B0 | A1 | B1
    __shared__ float rowred[2][128][2];
    __shared__ float colred[2][8][128];
    __shared__ int s_tk[2];                    // pipelined ticket ring

    const int tid = threadIdx.x;
    const int lane = tid & 31;
    const int wid = tid >> 5;                  // 0..15
    const int warp_m = wid & 7;                // 16-row slice
    const int warp_n = wid >> 3;               // 64-col slice
    const int g = lane >> 2;
    const int tg = lane & 3;

    const uint32_t a_off = (warp_m * 16 + (lane & 15)) * TSTRIDE + (lane >> 4) * 16;
    const uint32_t b_off = (warp_n * 64 + (lane & 7) + ((lane >> 4) & 1) * 8) * TSTRIDE
                         + ((lane >> 3) & 1) * 16;
    const float C1 = 2.8853900817779268f;   // 2*log2(e)

    // Prologue: ticket t0, prefetch ticket t1, issue loads for t0.
    if (tid == 0) s_tk[0] = atomicAdd(&g_ticket, 1);
    __syncthreads();
    int t = s_tk[0];
    if (tid == 0) s_tk[1] = atomicAdd(&g_ticket, 1);
    int rt = 0, jt = 0, buf = 0;
    if (t < NT) {
        tile_rc(t, rt, jt);
        load_tile_async(smBase, rt * 128, tid);
        if (jt != rt) load_tile_async(smBase + TILE_BYTES, jt * 128, tid);
        asm volatile("cp.async.commit_group;" ::: "memory");
    }

    while (t < NT) {
        asm volatile("cp.async.wait_group 0;" ::: "memory");
        __syncthreads();   // data visible; fences s_tk, scratch, buffers

        int t2 = s_tk[buf ^ 1];
        if (tid == 0) s_tk[buf] = atomicAdd(&g_ticket, 1);  // ticket t+2, hidden
        int rt2 = 0, jt2 = 0;
        if (t2 < NT) {
            tile_rc(t2, rt2, jt2);
            uint32_t nb = smBase + (buf ^ 1) * 2 * TILE_BYTES;
            load_tile_async(nb, rt2 * 128, tid);
            if (jt2 != rt2) load_tile_async(nb + TILE_BYTES, jt2 * 128, tid);
            asm volatile("cp.async.commit_group;" ::: "memory");
        }

        const uint32_t aBase = smBase + buf * 2 * TILE_BYTES;
        const uint32_t aAddr = aBase + a_off;
        const uint32_t bAddr = ((jt == rt) ? aBase : aBase + TILE_BYTES) + b_off;

        float acc[8][4];
        #pragma unroll
        for (int nf = 0; nf < 8; nf++)
            #pragma unroll
            for (int e = 0; e < 4; e++) acc[nf][e] = 0.f;

        #pragma unroll
        for (int ks = 0; ks < 8; ks++) {
            uint32_t a[4], b[4][4];
            ldm_x4(a, aAddr + ks * 32);
            #pragma unroll
            for (int np = 0; np < 4; np++)
                ldm_x4(b[np], bAddr + np * 16 * TSTRIDE + ks * 32);
            #pragma unroll
            for (int np = 0; np < 4; np++) {
                mma16816(acc[np * 2],     a, &b[np][0]);
                mma16816(acc[np * 2 + 1], a, &b[np][2]);
            }
        }

        float rs[2] = {0.f, 0.f};

        if (jt == rt) {
            // Diagonal tile: rows only, skip self element
            #pragma unroll
            for (int nf = 0; nf < 8; nf++)
                #pragma unroll
                for (int e = 0; e < 4; e++) {
                    int half = e >> 1;
                    int rloc = warp_m * 16 + half * 8 + g;
                    int cloc = warp_n * 64 + nf * 8 + tg * 2 + (e & 1);
                    float x = fmaf(acc[nf][e], C1, -C1);
                    float ex;
                    asm("ex2.approx.f32 %0, %1;" : "=f"(ex) : "f"(x));
                    if (cloc != rloc) rs[half] += ex;
                }
            #pragma unroll
            for (int i = 0; i < 2; i++) {
                rs[i] += __shfl_xor_sync(0xFFFFFFFFu, rs[i], 1);
                rs[i] += __shfl_xor_sync(0xFFFFFFFFu, rs[i], 2);
            }
            if (tg == 0) {
                #pragma unroll
                for (int half = 0; half < 2; half++)
                    rowred[buf][warp_m * 16 + half * 8 + g][warp_n] = rs[half];
            }
            __syncthreads();
            if (tid < 128)
                g_S[((size_t)rt * 64 + rt) * 128 + tid] =
                    rowred[buf][tid][0] + rowred[buf][tid][1];
        } else {
            float cs[8][2];
            #pragma unroll
            for (int nf = 0; nf < 8; nf++) { cs[nf][0] = 0.f; cs[nf][1] = 0.f; }

            if (jt == rt + 32) {
                // positive-pair tile: capture pos logits (row + symmetric partner)
                #pragma unroll
                for (int nf = 0; nf < 8; nf++)
                    #pragma unroll
                    for (int e = 0; e < 4; e++) {
                        int half = e >> 1;
                        int row = rt * 128 + warp_m * 16 + half * 8 + g;
                        int col = jt * 128 + warp_n * 64 + nf * 8 + tg * 2 + (e & 1);
                        float d = acc[nf][e];
                        float x = fmaf(d, C1, -C1);
                        float ex;
                        asm("ex2.approx.f32 %0, %1;" : "=f"(ex) : "f"(x));
                        rs[half] += ex;
                        cs[nf][e & 1] += ex;
                        if (col == row + BHALF) {
                            float p = 2.0f * d;
                            g_pos[row] = p;
                            g_pos[col] = p;
                        }
                    }
            } else {
                #pragma unroll
                for (int nf = 0; nf < 8; nf++)
                    #pragma unroll
                    for (int e = 0; e < 4; e++) {
                        float x = fmaf(acc[nf][e], C1, -C1);
                        float ex;
                        asm("ex2.approx.f32 %0, %1;" : "=f"(ex) : "f"(x));
                        rs[e >> 1] += ex;
                        cs[nf][e & 1] += ex;
                    }
            }

            #pragma unroll
            for (int i = 0; i < 2; i++) {
                rs[i] += __shfl_xor_sync(0xFFFFFFFFu, rs[i], 1);
                rs[i] += __shfl_xor_sync(0xFFFFFFFFu, rs[i], 2);
            }
            #pragma unroll
            for (int nf = 0; nf < 8; nf++)
                #pragma unroll
                for (int p = 0; p < 2; p++) {
                    float v = cs[nf][p];
                    v += __shfl_xor_sync(0xFFFFFFFFu, v, 4);
                    v += __shfl_xor_sync(0xFFFFFFFFu, v, 8);
                    v += __shfl_xor_sync(0xFFFFFFFFu, v, 16);
                    cs[nf][p] = v;
                }
            if (tg == 0) {
                #pragma unroll
                for (int half = 0; half < 2; half++)
                    rowred[buf][warp_m * 16 + half * 8 + g][warp_n] = rs[half];
            }
            if (g == 0) {
                #pragma unroll
                for (int nf = 0; nf < 8; nf++)
                    #pragma unroll
                    for (int p = 0; p < 2; p++)
                        colred[buf][warp_m][warp_n * 64 + nf * 8 + tg * 2 + p] = cs[nf][p];
            }
            __syncthreads();
            if (tid < 128) {
                g_S[((size_t)jt * 64 + rt) * 128 + tid] =
                    rowred[buf][tid][0] + rowred[buf][tid][1];
                float c = colred[buf][0][tid] + colred[buf][1][tid] +
                          colred[buf][2][tid] + colred[buf][3][tid] +
                          colred[buf][4][tid] + colred[buf][5][tid] +
                          colred[buf][6][tid] + colred[buf][7][tid];
                g_S[((size_t)rt * 64 + jt) * 128 + tid] = c;
            }
        }

        t = t2; rt = rt2; jt = jt2; buf ^= 1;
    }
}

// ---------------- Kernel 3: fused finalize (last block sums partials) ----------------
__global__ void k_final(float* __restrict__ out) {
    __shared__ float red[128];
    __shared__ int is_last;
    const int b = blockIdx.x;       // row block 0..63
    const int i = threadIdx.x;      // 0..127
    float s = 0.0f;
    #pragma unroll 16
    for (int a = 0; a < 64; a++)
        s += g_S[((size_t)a * 64 + b) * 128 + i];
    const int r = b * 128 + i;
    red[i] = 2.0f + __logf(s) - g_pos[r];
    __syncthreads();
    for (int off = 64; off > 0; off >>= 1) {
        if (i < off) red[i] += red[i + off];
        __syncthreads();
    }
    if (i == 0) {
        g_part[b] = red[0];
        __threadfence();
        is_last = (atomicAdd(&g_done, 1) == 63);
    }
    __syncthreads();
    if (is_last) {
        __threadfence();
        float v = (i < 64) ? g_part[i] : 0.0f;
        #pragma unroll
        for (int off = 16; off > 0; off >>= 1)
            v += __shfl_xor_sync(0xFFFFFFFFu, v, off);
        if ((i & 31) == 0) red[i >> 5] = v;
        __syncthreads();
        if (i == 0) {
            out[0] = (red[0] + red[1] + red[2] + red[3]) / (float)NROWS;
            g_done = 0;   // reset for next graph replay
        }
    }
}

extern "C" void kernel_launch(void* const* d_in, const int* in_sizes, int n_in,
                              void* d_out, int out_size) {
    const float* zi = (const float*)d_in[0];
    const float* zj = (const float*)d_in[1];
    float* out = (float*)d_out;

    const int smem_bytes = 4 * TILE_BYTES;   // 139264
    cudaFuncSetAttribute(k_gram, cudaFuncAttributeMaxDynamicSharedMemorySize, smem_bytes);

    k_normalize<<<256, 256>>>(zi, zj);
    k_gram<<<148, 512, smem_bytes>>>();
    k_final<<<64, 128>>>(out);
}

// round 15
// speedup vs baseline: 1.3139x; 1.3139x over previous
#include <cuda_runtime.h>
#include <cuda_bf16.h>
#include <cstdint>

// SimCLR loss via mma.sync bf16, upper-triangle Gram, ticket-balanced
// persistent CTAs, 2 CTAs/SM for cross-CTA tensor/epilogue overlap.
// B=4096, D=128, N=8192, T=0.5.
//   k1: row-normalize -> g_znh bf16 (2MB, L2-resident); resets ticket
//   k2: 296 persistent CTAs (2/SM, 256 thr) pull tiles (rt<=jt); per tile:
//       HMMA 128x128x128 (single-buffered A+B; next tile's loads issued
//       between k-loop and epilogue), exp(2*cos-2), row-part -> S[jt][rt],
//       col-part -> S[rt][jt]  (per-tile slots => deterministic)
//   k3: fused finalize: per-row sums + log - pos; last block sums partials

#define NROWS 8192
#define BHALF 4096
#define NT 2080              // 64*65/2 upper-triangle 128x128 tiles
#define TSTRIDE 272          // smem tile row stride bytes (128 bf16 + 16B pad)
#define TILE_BYTES (128 * TSTRIDE)

__device__ uint4 g_znh[NROWS * 16];
__device__ float g_S[64 * 64 * 128];   // [a][b][i]: contribution to row b*128+i from block a
__device__ float g_pos[NROWS];
__device__ float g_part[64];
__device__ int g_ticket;
__device__ int g_done;

__device__ __forceinline__ uint32_t smem_u32(const void* p) {
    uint32_t a;
    asm("{ .reg .u64 t; cvta.to.shared.u64 t, %1; cvt.u32.u64 %0, t; }" : "=r"(a) : "l"(p));
    return a;
}
__device__ __forceinline__ void cpasync16(uint32_t dst, const void* src) {
    asm volatile("cp.async.cg.shared.global [%0], [%1], 16;"
                 :: "r"(dst), "l"(__cvta_generic_to_global(src)) : "memory");
}
__device__ __forceinline__ void ldm_x4(uint32_t* r, uint32_t addr) {
    asm volatile("ldmatrix.sync.aligned.m8n8.x4.shared.b16 {%0,%1,%2,%3}, [%4];"
                 : "=r"(r[0]), "=r"(r[1]), "=r"(r[2]), "=r"(r[3]) : "r"(addr));
}
__device__ __forceinline__ void mma16816(float* c, const uint32_t* a, const uint32_t* b) {
    asm volatile(
        "mma.sync.aligned.m16n8k16.row.col.f32.bf16.bf16.f32 "
        "{%0,%1,%2,%3}, {%4,%5,%6,%7}, {%8,%9}, {%0,%1,%2,%3};"
        : "+f"(c[0]), "+f"(c[1]), "+f"(c[2]), "+f"(c[3])
        : "r"(a[0]), "r"(a[1]), "r"(a[2]), "r"(a[3]), "r"(b[0]), "r"(b[1]));
}

// tile index t (0..2079) -> (rt, jt), rt<=jt; offset(r) = r*(129-r)/2
__device__ __forceinline__ void tile_rc(int t, int& rt, int& jt) {
    int r = (int)((129.0f - sqrtf((float)(16641 - 8 * t))) * 0.5f);
    while (r > 0 && r * (129 - r) / 2 > t) r--;
    while ((r + 1) * (129 - (r + 1)) / 2 <= t) r++;
    rt = r;
    jt = r + (t - r * (129 - r) / 2);
}

// ---------------- Kernel 1: normalize -> bf16 ----------------
__global__ void k_normalize(const float* __restrict__ zi, const float* __restrict__ zj) {
    if (blockIdx.x == 0 && threadIdx.x == 0) g_ticket = 0;   // reset ticket each launch
    int gw = (blockIdx.x * blockDim.x + threadIdx.x) >> 5;   // 0..2047
    int lane = threadIdx.x & 31;
    int r0 = gw * 4;
    if (r0 >= NROWS) return;
    const float* base = (r0 < BHALF) ? zi : (zj - (size_t)BHALF * 128);
    float4 v[4];
    #pragma unroll
    for (int k = 0; k < 4; k++)
        v[k] = reinterpret_cast<const float4*>(base + (size_t)(r0 + k) * 128)[lane];
    #pragma unroll
    for (int k = 0; k < 4; k++) {
        float ss = v[k].x * v[k].x + v[k].y * v[k].y + v[k].z * v[k].z + v[k].w * v[k].w;
        #pragma unroll
        for (int off = 16; off > 0; off >>= 1)
            ss += __shfl_xor_sync(0xFFFFFFFFu, ss, off);
        float s = 1.0f / fmaxf(sqrtf(ss), 1e-8f);
        __nv_bfloat162 h0 = __floats2bfloat162_rn(v[k].x * s, v[k].y * s);
        __nv_bfloat162 h1 = __floats2bfloat162_rn(v[k].z * s, v[k].w * s);
        uint2 o;
        o.x = *reinterpret_cast<uint32_t*>(&h0);
        o.y = *reinterpret_cast<uint32_t*>(&h1);
        reinterpret_cast<uint2*>(g_znh)[(size_t)(r0 + k) * 32 + lane] = o;
    }
}

__device__ __forceinline__ void load_tile_async(uint32_t sm_tile, int row0, int tid) {
    #pragma unroll
    for (int it = 0; it < 8; it++) {
        int i = tid + it * 256;
        int row = i >> 4;
        int c = i & 15;
        cpasync16(sm_tile + row * TSTRIDE + c * 16, &g_znh[(size_t)(row0 + row) * 16 + c]);
    }
}

// ---------------- Kernel 2: persistent triangular Gram (2 CTAs/SM) ----------------
__global__ void __launch_bounds__(256, 2) k_gram(void) {
    extern __shared__ char smem[];
    const uint32_t smA = smem_u32(smem);       // A | B single buffer
    const uint32_t smB = smA + TILE_BYTES;
    __shared__ float rowred[128][2];
    __shared__ float colred[4][128];
    __shared__ int s_tk[2];                    // pipelined ticket ring

    const int tid = threadIdx.x;
    const int lane = tid & 31;
    const int wid = tid >> 5;
    const int warp_m = wid & 3;                // 32-row slice
    const int warp_n = wid >> 2;               // 64-col slice
    const int g = lane >> 2;
    const int tg = lane & 3;

    const uint32_t a_off = (warp_m * 32 + (lane & 15)) * TSTRIDE + (lane >> 4) * 16;
    const uint32_t b_off = (warp_n * 64 + (lane & 7) + ((lane >> 4) & 1) * 8) * TSTRIDE
                         + ((lane >> 3) & 1) * 16;
    const float C1 = 2.8853900817779268f;   // 2*log2(e)

    // Prologue: ticket t0, prefetch ticket t1, issue loads for t0.
    if (tid == 0) s_tk[0] = atomicAdd(&g_ticket, 1);
    __syncthreads();
    int t = s_tk[0];
    if (tid == 0) s_tk[1] = atomicAdd(&g_ticket, 1);
    int rt = 0, jt = 0, k = 0;
    if (t < NT) {
        tile_rc(t, rt, jt);
        load_tile_async(smA, rt * 128, tid);
        if (jt != rt) load_tile_async(smB, jt * 128, tid);
        asm volatile("cp.async.commit_group;" ::: "memory");
    }

    while (t < NT) {
        asm volatile("cp.async.wait_group 0;" ::: "memory");
        __syncthreads();   // tile data visible; fences s_tk + scratch reuse

        const uint32_t aAddr = smA + a_off;
        const uint32_t bAddr = ((jt == rt) ? smA : smB) + b_off;

        float acc[2][8][4];
        #pragma unroll
        for (int mf = 0; mf < 2; mf++)
            #pragma unroll
            for (int nf = 0; nf < 8; nf++)
                #pragma unroll
                for (int e = 0; e < 4; e++) acc[mf][nf][e] = 0.f;

        #pragma unroll
        for (int ks = 0; ks < 8; ks++) {
            uint32_t a[2][4], b[4][4];
            ldm_x4(a[0], aAddr + ks * 32);
            ldm_x4(a[1], aAddr + 16 * TSTRIDE + ks * 32);
            #pragma unroll
            for (int np = 0; np < 4; np++)
                ldm_x4(b[np], bAddr + np * 16 * TSTRIDE + ks * 32);
            #pragma unroll
            for (int mf = 0; mf < 2; mf++)
                #pragma unroll
                for (int np = 0; np < 4; np++) {
                    mma16816(acc[mf][np * 2],     a[mf], &b[np][0]);
                    mma16816(acc[mf][np * 2 + 1], a[mf], &b[np][2]);
                }
        }
        __syncthreads();   // all warps done reading the buffer

        // Issue next tile's loads NOW (overlap with epilogue below).
        int t2 = s_tk[k ^ 1];
        if (tid == 0) s_tk[k] = atomicAdd(&g_ticket, 1);   // ticket t+2
        int rt2 = 0, jt2 = 0;
        if (t2 < NT) {
            tile_rc(t2, rt2, jt2);
            load_tile_async(smA, rt2 * 128, tid);
            if (jt2 != rt2) load_tile_async(smB, jt2 * 128, tid);
            asm volatile("cp.async.commit_group;" ::: "memory");
        }

        float rs[4] = {0.f, 0.f, 0.f, 0.f};

        if (jt == rt) {
            // Diagonal tile: rows only, skip self element
            #pragma unroll
            for (int mf = 0; mf < 2; mf++)
                #pragma unroll
                for (int nf = 0; nf < 8; nf++)
                    #pragma unroll
                    for (int e = 0; e < 4; e++) {
                        int half = e >> 1;
                        int rloc = warp_m * 32 + mf * 16 + half * 8 + g;
                        int cloc = warp_n * 64 + nf * 8 + tg * 2 + (e & 1);
                        float x = fmaf(acc[mf][nf][e], C1, -C1);
                        float ex;
                        asm("ex2.approx.f32 %0, %1;" : "=f"(ex) : "f"(x));
                        if (cloc != rloc) rs[mf * 2 + half] += ex;
                    }
            #pragma unroll
            for (int i = 0; i < 4; i++) {
                rs[i] += __shfl_xor_sync(0xFFFFFFFFu, rs[i], 1);
                rs[i] += __shfl_xor_sync(0xFFFFFFFFu, rs[i], 2);
            }
            if (tg == 0) {
                #pragma unroll
                for (int mf = 0; mf < 2; mf++)
                    #pragma unroll
                    for (int half = 0; half < 2; half++)
                        rowred[warp_m * 32 + mf * 16 + half * 8 + g][warp_n] =
                            rs[mf * 2 + half];
            }
            __syncthreads();
            if (tid < 128)
                g_S[((size_t)rt * 64 + rt) * 128 + tid] =
                    rowred[tid][0] + rowred[tid][1];
        } else {
            float cs[8][2];
            #pragma unroll
            for (int nf = 0; nf < 8; nf++) { cs[nf][0] = 0.f; cs[nf][1] = 0.f; }

            if (jt == rt + 32) {
                // positive-pair tile: capture pos logits (row + symmetric partner)
                #pragma unroll
                for (int mf = 0; mf < 2; mf++)
                    #pragma unroll
                    for (int nf = 0; nf < 8; nf++)
                        #pragma unroll
                        for (int e = 0; e < 4; e++) {
                            int half = e >> 1;
                            int row = rt * 128 + warp_m * 32 + mf * 16 + half * 8 + g;
                            int col = jt * 128 + warp_n * 64 + nf * 8 + tg * 2 + (e & 1);
                            float d = acc[mf][nf][e];
                            float x = fmaf(d, C1, -C1);
                            float ex;
                            asm("ex2.approx.f32 %0, %1;" : "=f"(ex) : "f"(x));
                            rs[mf * 2 + half] += ex;
                            cs[nf][e & 1] += ex;
                            if (col == row + BHALF) {
                                float p = 2.0f * d;
                                g_pos[row] = p;
                                g_pos[col] = p;
                            }
                        }
            } else {
                #pragma unroll
                for (int mf = 0; mf < 2; mf++)
                    #pragma unroll
                    for (int nf = 0; nf < 8; nf++)
                        #pragma unroll
                        for (int e = 0; e < 4; e++) {
                            float x = fmaf(acc[mf][nf][e], C1, -C1);
                            float ex;
                            asm("ex2.approx.f32 %0, %1;" : "=f"(ex) : "f"(x));
                            rs[mf * 2 + (e >> 1)] += ex;
                            cs[nf][e & 1] += ex;
                        }
            }

            #pragma unroll
            for (int i = 0; i < 4; i++) {
                rs[i] += __shfl_xor_sync(0xFFFFFFFFu, rs[i], 1);
                rs[i] += __shfl_xor_sync(0xFFFFFFFFu, rs[i], 2);
            }
            #pragma unroll
            for (int nf = 0; nf < 8; nf++)
                #pragma unroll
                for (int p = 0; p < 2; p++) {
                    float v = cs[nf][p];
                    v += __shfl_xor_sync(0xFFFFFFFFu, v, 4);
                    v += __shfl_xor_sync(0xFFFFFFFFu, v, 8);
                    v += __shfl_xor_sync(0xFFFFFFFFu, v, 16);
                    cs[nf][p] = v;
                }
            if (tg == 0) {
                #pragma unroll
                for (int mf = 0; mf < 2; mf++)
                    #pragma unroll
                    for (int half = 0; half < 2; half++)
                        rowred[warp_m * 32 + mf * 16 + half * 8 + g][warp_n] =
                            rs[mf * 2 + half];
            }
            if (g == 0) {
                #pragma unroll
                for (int nf = 0; nf < 8; nf++)
                    #pragma unroll
                    for (int p = 0; p < 2; p++)
                        colred[warp_m][warp_n * 64 + nf * 8 + tg * 2 + p] = cs[nf][p];
            }
            __syncthreads();
            if (tid < 128) {
                g_S[((size_t)jt * 64 + rt) * 128 + tid] =
                    rowred[tid][0] + rowred[tid][1];
                g_S[((size_t)rt * 64 + jt) * 128 + tid] =
                    colred[0][tid] + colred[1][tid] +
                    colred[2][tid] + colred[3][tid];
            }
        }

        t = t2; rt = rt2; jt = jt2; k ^= 1;
    }
}

// ---------------- Kernel 3: fused finalize (last block sums partials) ----------------
__global__ void k_final(float* __restrict__ out) {
    __shared__ float red[128];
    __shared__ int is_last;
    const int b = blockIdx.x;       // row block 0..63
    const int i = threadIdx.x;      // 0..127
    float s = 0.0f;
    #pragma unroll 16
    for (int a = 0; a < 64; a++)
        s += g_S[((size_t)a * 64 + b) * 128 + i];
    const int r = b * 128 + i;
    red[i] = 2.0f + __logf(s) - g_pos[r];
    __syncthreads();
    for (int off = 64; off > 0; off >>= 1) {
        if (i < off) red[i] += red[i + off];
        __syncthreads();
    }
    if (i == 0) {
        g_part[b] = red[0];
        __threadfence();
        is_last = (atomicAdd(&g_done, 1) == 63);
    }
    __syncthreads();
    if (is_last) {
        __threadfence();
        float v = (i < 64) ? g_part[i] : 0.0f;
        #pragma unroll
        for (int off = 16; off > 0; off >>= 1)
            v += __shfl_xor_sync(0xFFFFFFFFu, v, off);
        if ((i & 31) == 0) red[i >> 5] = v;
        __syncthreads();
        if (i == 0) {
            out[0] = (red[0] + red[1] + red[2] + red[3]) / (float)NROWS;
            g_done = 0;   // reset for next graph replay
        }
    }
}

extern "C" void kernel_launch(void* const* d_in, const int* in_sizes, int n_in,
                              void* d_out, int out_size) {
    const float* zi = (const float*)d_in[0];
    const float* zj = (const float*)d_in[1];
    float* out = (float*)d_out;

    const int smem_bytes = 2 * TILE_BYTES;   // 69632 (2 CTAs/SM fit)
    cudaFuncSetAttribute(k_gram, cudaFuncAttributeMaxDynamicSharedMemorySize, smem_bytes);

    k_normalize<<<256, 256>>>(zi, zj);
    k_gram<<<296, 256, smem_bytes>>>();
    k_final<<<64, 128>>>(out);
}